// round 11
// baseline (speedup 1.0000x reference)
#include <cuda_runtime.h>

#define B 8
#define N 2048
#define BN (B * N)
#define DELTA 1e-7f

#define TPB 512
#define NWARP (TPB / 32)                // 16
#define CROWS 4                         // rows per chunk: 4*2048*4B = 32KB
#define NCHUNKS (N / CROWS)             // 512 chunks per batch
#define CTAS_PER_B 38
#define GRID (B * CTAS_PER_B)           // 304 CTAs = 2 per SM on 152 SMs
#define MAXCH ((NCHUNKS + CTAS_PER_B - 1) / CTAS_PER_B)   // 14

// Persistent scratch (__device__ globals per allocation rules).
__device__ float  g_odout1[BN];
__device__ float  g_odout2[BN];
__device__ float  g_pop1[BN];
__device__ float4 g_sir6[BN * 2];   // SIR after iter 0 (6 floats in 2x float4)
__device__ float  g_colA[BN * 4];   // iter0 colsums [OD_in, SIR_in*3] (zeroed by pass2)
__device__ float  g_colB[BN * 8];   // iter1 colsums [OD_in, SIR_in*6, pad] (zeroed by final)

__device__ __forceinline__ float dnn(float n, float d) { return (d == 0.0f) ? 0.0f : n / d; }

// ---------------------------------------------------------------------------
// Pass 1 (iteration 0, K=4). Register-resident 32KB chunks, 2 CTAs/SM.
// ---------------------------------------------------------------------------
__global__ void __launch_bounds__(TPB, 2) pass1_kernel(
    const float* __restrict__ inp, const float* __restrict__ od_all)
{
    __shared__ float  s_sum[CROWS * NWARP];  // per-warp row partials
    __shared__ float4 s_w[CROWS];            // weights for current chunk
    __shared__ float4 s_st[MAXCH * CROWS];   // prefetched input features

    const int b    = blockIdx.x / CTAS_PER_B;
    const int slot = blockIdx.x % CTAS_PER_B;
    const int tid  = threadIdx.x;
    const int warp = tid >> 5, lane = tid & 31;
    const float4* ODb = reinterpret_cast<const float4*>(od_all + (size_t)(b * 2) * N * N);
    const int nch = (NCHUNKS - 1 - slot) / CTAS_PER_B + 1;   // 13 or 14

    for (int L = tid; L < nch * CROWS; L += TPB) {
        int i = (slot + (L >> 2) * CTAS_PER_B) * CROWS + (L & 3);
        s_st[L] = reinterpret_cast<const float4*>(inp)[b * N + i];
    }
    __syncthreads();

    float acc[4][4] = {};

    for (int c = 0; c < nch; c++) {
        // load chunk c directly to registers (coalesced LDG.128)
        const float4* p = ODb + (size_t)(slot + c * CTAS_PER_B) * CROWS * (N / 4) + tid;
        float4 d[CROWS];
#pragma unroll
        for (int r = 0; r < CROWS; r++) d[r] = p[r * (N / 4)];

        // warp-level row partials via shfl
#pragma unroll
        for (int r = 0; r < CROWS; r++) {
            float s = (d[r].x + d[r].y) + (d[r].z + d[r].w);
#pragma unroll
            for (int o = 16; o; o >>= 1) s += __shfl_xor_sync(0xffffffffu, s, o);
            if (lane == 0) s_sum[r * NWARP + warp] = s;
        }
        __syncthreads();   // bar1: partials visible

        // warps 0..3 reduce their row, compute weights
        if (warp < CROWS) {
            float s = (lane < NWARP) ? s_sum[warp * NWARP + lane] : 0.0f;
#pragma unroll
            for (int o = 8; o; o >>= 1) s += __shfl_xor_sync(0xffffffffu, s, o);
            if (lane == 0) {
                float4 f = s_st[c * CROWS + warp];
                int gi = b * N + (slot + c * CTAS_PER_B) * CROWS + warp;
                float ratio = f.x / (DELTA + s);
                float sc = ratio < 1.0f ? ratio : 1.0f;
                g_odout1[gi] = sc * s;
                float inv = 1.0f / (DELTA + f.x);
                s_w[warp] = make_float4(sc, sc * (f.y * inv),
                                        sc * (f.z * inv), sc * (f.w * inv));
            }
        }
        __syncthreads();   // bar2: weights visible

        // K=4 weighted accumulation straight from registers
#pragma unroll
        for (int r = 0; r < CROWS; r++) {
            float4 v = d[r];
            float4 w = s_w[r];
            float wk[4] = {w.x, w.y, w.z, w.w};
#pragma unroll
            for (int k = 0; k < 4; k++) {
                acc[0][k] = fmaf(v.x, wk[k], acc[0][k]);
                acc[1][k] = fmaf(v.y, wk[k], acc[1][k]);
                acc[2][k] = fmaf(v.z, wk[k], acc[2][k]);
                acc[3][k] = fmaf(v.w, wk[k], acc[3][k]);
            }
        }
        // s_sum(c+1)/s_w(c+1) rewrites are fenced by bar1(c+1)/bar1+2(c+1).
    }

#pragma unroll
    for (int cc = 0; cc < 4; cc++) {
        float* dst = g_colA + ((size_t)b * N + tid * 4 + cc) * 4;
#pragma unroll
        for (int k = 0; k < 4; k++) atomicAdd(dst + k, acc[cc][k]);
    }
}

// ---------------------------------------------------------------------------
// Pass 2 (iteration 1, K=7). Fuses update<3> in the state prefetch.
// ---------------------------------------------------------------------------
__global__ void __launch_bounds__(TPB, 2) pass2_kernel(
    const float* __restrict__ inp, const float* __restrict__ od_all)
{
    __shared__ float  s_sum[CROWS * NWARP];
    __shared__ float4 s_w[CROWS * 2];        // 7 weights per row (2 float4)
    __shared__ float4 s_st[MAXCH * CROWS * 2];

    const int b    = blockIdx.x / CTAS_PER_B;
    const int slot = blockIdx.x % CTAS_PER_B;
    const int tid  = threadIdx.x;
    const int warp = tid >> 5, lane = tid & 31;
    const float4* ODb = reinterpret_cast<const float4*>(od_all + (size_t)(b * 2 + 1) * N * N);
    const int nch = (NCHUNKS - 1 - slot) / CTAS_PER_B + 1;

    // One-time prefetch + fused iter-0 state update; re-zero colA for replay
    for (int L = tid; L < nch * CROWS; L += TPB) {
        int i  = (slot + (L >> 2) * CTAS_PER_B) * CROWS + (L & 3);
        int gi = b * N + i;
        float4 f   = reinterpret_cast<const float4*>(inp)[gi];
        float4 csA = reinterpret_cast<float4*>(g_colA)[gi];
        reinterpret_cast<float4*>(g_colA)[gi] = make_float4(0, 0, 0, 0);
        float od1 = g_odout1[gi];
        float inv0 = 1.0f / (DELTA + f.x);
        float s60 = f.y - od1 * (f.y * inv0);
        float s61 = f.z - od1 * (f.z * inv0);
        float s62 = f.w - od1 * (f.w * inv0);
        float pop1 = f.x - od1 + csA.x;
        s_st[L * 2 + 0] = make_float4(pop1, s60, s61, s62);
        s_st[L * 2 + 1] = make_float4(csA.y, csA.z, csA.w, 0.0f);
        g_pop1[gi] = pop1;
        g_sir6[gi * 2 + 0] = make_float4(s60, s61, s62, csA.y);
        g_sir6[gi * 2 + 1] = make_float4(csA.z, csA.w, 0.0f, 0.0f);
    }
    __syncthreads();

    float acc[4][7] = {};

    for (int c = 0; c < nch; c++) {
        const float4* p = ODb + (size_t)(slot + c * CTAS_PER_B) * CROWS * (N / 4) + tid;
        float4 d[CROWS];
#pragma unroll
        for (int r = 0; r < CROWS; r++) d[r] = p[r * (N / 4)];

#pragma unroll
        for (int r = 0; r < CROWS; r++) {
            float s = (d[r].x + d[r].y) + (d[r].z + d[r].w);
#pragma unroll
            for (int o = 16; o; o >>= 1) s += __shfl_xor_sync(0xffffffffu, s, o);
            if (lane == 0) s_sum[r * NWARP + warp] = s;
        }
        __syncthreads();   // bar1

        if (warp < CROWS) {
            float s = (lane < NWARP) ? s_sum[warp * NWARP + lane] : 0.0f;
#pragma unroll
            for (int o = 8; o; o >>= 1) s += __shfl_xor_sync(0xffffffffu, s, o);
            if (lane == 0) {
                float4 a  = s_st[(c * CROWS + warp) * 2 + 0];   // pop1, s6[0..2]
                float4 bb = s_st[(c * CROWS + warp) * 2 + 1];   // s6[3..5]
                int gi = b * N + (slot + c * CTAS_PER_B) * CROWS + warp;
                float ratio = a.x / (DELTA + s);
                float sc = ratio < 1.0f ? ratio : 1.0f;
                g_odout2[gi] = sc * s;
                float inv = 1.0f / (DELTA + a.x);
                s_w[warp * 2 + 0] = make_float4(sc, sc * (a.y * inv),
                                                sc * (a.z * inv), sc * (a.w * inv));
                s_w[warp * 2 + 1] = make_float4(sc * (bb.x * inv), sc * (bb.y * inv),
                                                sc * (bb.z * inv), 0.0f);
            }
        }
        __syncthreads();   // bar2

#pragma unroll
        for (int r = 0; r < CROWS; r++) {
            float4 v  = d[r];
            float4 wa = s_w[r * 2 + 0];
            float4 wb = s_w[r * 2 + 1];
            float wk[7] = {wa.x, wa.y, wa.z, wa.w, wb.x, wb.y, wb.z};
#pragma unroll
            for (int k = 0; k < 7; k++) {
                acc[0][k] = fmaf(v.x, wk[k], acc[0][k]);
                acc[1][k] = fmaf(v.y, wk[k], acc[1][k]);
                acc[2][k] = fmaf(v.z, wk[k], acc[2][k]);
                acc[3][k] = fmaf(v.w, wk[k], acc[3][k]);
            }
        }
    }

#pragma unroll
    for (int cc = 0; cc < 4; cc++) {
        float* dst = g_colB + ((size_t)b * N + tid * 4 + cc) * 8;
#pragma unroll
        for (int k = 0; k < 7; k++) atomicAdd(dst + k, acc[cc][k]);
    }
}

// ---------------------------------------------------------------------------
// Final: fuses update<6> + GEMM(12->64) + relu + concat(pop). Re-zeros colB.
// ---------------------------------------------------------------------------
__global__ void __launch_bounds__(256) final_kernel(
    const float* __restrict__ kern,
    const float* __restrict__ bias,
    float* __restrict__ out)
{
    __shared__ float s_kern[12 * 64];
    const int tid = threadIdx.x;
    for (int t = tid; t < 12 * 64; t += 256) s_kern[t] = kern[t];
    __syncthreads();

    const int rowl = tid >> 6;
    const int c    = tid & 63;
    const int gi   = blockIdx.x * 4 + rowl;

    float pop1   = g_pop1[gi];
    float odout2 = g_odout2[gi];
    float4 a   = g_sir6[gi * 2 + 0];
    float4 b4  = g_sir6[gi * 2 + 1];
    float4 cb0 = reinterpret_cast<const float4*>(g_colB)[gi * 2 + 0];
    float4 cb1 = reinterpret_cast<const float4*>(g_colB)[gi * 2 + 1];

    float dp1 = DELTA + pop1;
    float s12[12];
    s12[0] = a.x  - odout2 * dnn(a.x,  dp1);
    s12[1] = a.y  - odout2 * dnn(a.y,  dp1);
    s12[2] = a.z  - odout2 * dnn(a.z,  dp1);
    s12[3] = a.w  - odout2 * dnn(a.w,  dp1);
    s12[4] = b4.x - odout2 * dnn(b4.x, dp1);
    s12[5] = b4.y - odout2 * dnn(b4.y, dp1);
    s12[6]  = cb0.y; s12[7]  = cb0.z; s12[8]  = cb0.w;
    s12[9]  = cb1.x; s12[10] = cb1.y; s12[11] = cb1.z;

    float acc = __ldg(&bias[c]);
#pragma unroll
    for (int f = 0; f < 12; f++)
        acc = fmaf(s12[f], s_kern[f * 64 + c], acc);
    acc = fmaxf(acc, 0.0f);

    float* orow = out + (size_t)gi * 65;
    orow[1 + c] = acc;
    if (c == 0) orow[0] = pop1 - odout2 + cb0.x;

    __syncthreads();                  // all colB reads done before re-zero
    if (c < 8) g_colB[gi * 8 + c] = 0.0f;
}

// ---------------------------------------------------------------------------
extern "C" void kernel_launch(void* const* d_in, const int* in_sizes, int n_in,
                              void* d_out, int out_size) {
    const float* inp  = (const float*)d_in[0];  // input_feature (8,2048,4)
    const float* od   = (const float*)d_in[1];  // OD_all (8,2,2048,2048)
    const float* kern = (const float*)d_in[2];  // kernel (12,64)
    const float* bias = (const float*)d_in[3];  // bias (64)
    float* out = (float*)d_out;                 // (8,2048,65)

    pass1_kernel<<<GRID, TPB>>>(inp, od);
    pass2_kernel<<<GRID, TPB>>>(inp, od);
    final_kernel<<<BN / 4, 256>>>(kern, bias, out);
}

// round 12
// speedup vs baseline: 1.3682x; 1.3682x over previous
#include <cuda_runtime.h>

#define B 8
#define N 2048
#define BN (B * N)
#define DELTA 1e-7f

#define TPB 512
#define NWARP (TPB / 32)                // 16
#define CROWS 8                         // rows per chunk: 8*2048*4B = 64KB
#define NCHUNKS (N / CROWS)             // 256 chunks per batch
#define CTAS_PER_B 19
#define GRID (B * CTAS_PER_B)           // 152 CTAs = 1 per SM
#define MAXCH ((NCHUNKS + CTAS_PER_B - 1) / CTAS_PER_B)   // 14

typedef unsigned long long u64;

// Persistent scratch (__device__ globals per allocation rules).
__device__ float  g_odout1[BN];
__device__ float  g_odout2[BN];
__device__ float  g_pop1[BN];
__device__ float4 g_sir6[BN * 2];   // SIR after iter 0 (6 floats in 2x float4)
__device__ float  g_colA[BN * 4];   // iter0 colsums [OD_in, SIR_in*3] (zeroed by pass2)
__device__ float  g_colB[BN * 8];   // iter1 colsums [OD_in, SIR_in*6, pad] (zeroed by final)

__device__ __forceinline__ float dnn(float n, float d) { return (d == 0.0f) ? 0.0f : n / d; }

// ---- packed fp32x2 helpers (sm_103a dual-FMA; PTX-only, ptxas won't fuse) ----
__device__ __forceinline__ u64 pack2(float lo, float hi) {
    u64 r; asm("mov.b64 %0, {%1, %2};" : "=l"(r) : "f"(lo), "f"(hi)); return r;
}
__device__ __forceinline__ void unpack2(u64 v, float& lo, float& hi) {
    asm("mov.b64 {%0, %1}, %2;" : "=f"(lo), "=f"(hi) : "l"(v));
}
__device__ __forceinline__ void fma2(u64& d, u64 a, u64 b) {
    asm("fma.rn.f32x2 %0, %1, %2, %0;" : "+l"(d) : "l"(a), "l"(b));
}

// ---------------------------------------------------------------------------
// Pass 1 (iteration 0, K=4). Register double-buffered chunks + packed FMA.
// ---------------------------------------------------------------------------
__global__ void __launch_bounds__(TPB, 1) pass1_kernel(
    const float* __restrict__ inp, const float* __restrict__ od_all)
{
    __shared__ float  s_sum[CROWS * NWARP];  // per-warp row partials (shfl-produced)
    __shared__ u64    s_wp[CROWS * 4];       // packed (w,w) weights per row
    __shared__ float4 s_st[MAXCH * CROWS];   // prefetched input features

    const int b    = blockIdx.x / CTAS_PER_B;
    const int slot = blockIdx.x % CTAS_PER_B;
    const int tid  = threadIdx.x;
    const int warp = tid >> 5, lane = tid & 31;
    const float4* ODb = reinterpret_cast<const float4*>(od_all + (size_t)(b * 2) * N * N);
    const int nch = (NCHUNKS - 1 - slot) / CTAS_PER_B + 1;   // 13 or 14

    for (int L = tid; L < nch * CROWS; L += TPB) {
        int i = (slot + (L >> 3) * CTAS_PER_B) * CROWS + (L & 7);
        s_st[L] = reinterpret_cast<const float4*>(inp)[b * N + i];
    }
    __syncthreads();

    float4 dA[CROWS], dB[CROWS];
    {   // prologue: chunk 0 -> dA
        const float4* p = ODb + (size_t)slot * CROWS * (N / 4) + tid;
#pragma unroll
        for (int r = 0; r < CROWS; r++) dA[r] = p[r * (N / 4)];
    }

    u64 acc[2][4] = {};   // [col-pair][k]; 0 bits == (+0.f,+0.f)

    auto body = [&](float4 (&cur)[CROWS], float4 (&nxt)[CROWS], int c) {
        if (c + 1 < nch) {   // prefetch chunk c+1 into the other register set
            const float4* p = ODb + (size_t)(slot + (c + 1) * CTAS_PER_B) * CROWS * (N / 4) + tid;
#pragma unroll
            for (int r = 0; r < CROWS; r++) nxt[r] = p[r * (N / 4)];
        }
        // warp-level row partials via shfl
#pragma unroll
        for (int r = 0; r < CROWS; r++) {
            float s = (cur[r].x + cur[r].y) + (cur[r].z + cur[r].w);
#pragma unroll
            for (int o = 16; o; o >>= 1) s += __shfl_xor_sync(0xffffffffu, s, o);
            if (lane == 0) s_sum[r * NWARP + warp] = s;
        }
        __syncthreads();   // bar1: partials visible

        if (warp < CROWS) {
            float s = (lane < NWARP) ? s_sum[warp * NWARP + lane] : 0.0f;
#pragma unroll
            for (int o = 8; o; o >>= 1) s += __shfl_xor_sync(0xffffffffu, s, o);
            if (lane == 0) {
                float4 f = s_st[c * CROWS + warp];
                int gi = b * N + (slot + c * CTAS_PER_B) * CROWS + warp;
                float ratio = f.x / (DELTA + s);
                float sc = ratio < 1.0f ? ratio : 1.0f;
                g_odout1[gi] = sc * s;
                float inv = 1.0f / (DELTA + f.x);
                float w1 = sc * (f.y * inv), w2 = sc * (f.z * inv), w3 = sc * (f.w * inv);
                s_wp[warp * 4 + 0] = pack2(sc, sc);
                s_wp[warp * 4 + 1] = pack2(w1, w1);
                s_wp[warp * 4 + 2] = pack2(w2, w2);
                s_wp[warp * 4 + 3] = pack2(w3, w3);
            }
        }
        __syncthreads();   // bar2: packed weights visible

        // packed K=4 accumulation: 8 FFMA2 per row (vs 16 FFMA)
#pragma unroll
        for (int r = 0; r < CROWS; r++) {
            u64 v01 = pack2(cur[r].x, cur[r].y);
            u64 v23 = pack2(cur[r].z, cur[r].w);
            const ulonglong2* wp = reinterpret_cast<const ulonglong2*>(s_wp + r * 4);
            ulonglong2 wa = wp[0], wb = wp[1];
            fma2(acc[0][0], v01, wa.x); fma2(acc[1][0], v23, wa.x);
            fma2(acc[0][1], v01, wa.y); fma2(acc[1][1], v23, wa.y);
            fma2(acc[0][2], v01, wb.x); fma2(acc[1][2], v23, wb.x);
            fma2(acc[0][3], v01, wb.y); fma2(acc[1][3], v23, wb.y);
        }
    };

    for (int c = 0; c < nch; c += 2) {
        body(dA, dB, c);
        if (c + 1 < nch) body(dB, dA, c + 1);
    }

    // flush: unpack and atomically add (cols j4+0..3)
#pragma unroll
    for (int h = 0; h < 2; h++) {
#pragma unroll
        for (int k = 0; k < 4; k++) {
            float lo, hi;
            unpack2(acc[h][k], lo, hi);
            atomicAdd(g_colA + ((size_t)b * N + tid * 4 + h * 2 + 0) * 4 + k, lo);
            atomicAdd(g_colA + ((size_t)b * N + tid * 4 + h * 2 + 1) * 4 + k, hi);
        }
    }
}

// ---------------------------------------------------------------------------
// Pass 2 (iteration 1, K=7). Fuses update<3>; packed FMA (14 FFMA2/row vs 28).
// ---------------------------------------------------------------------------
__global__ void __launch_bounds__(TPB, 1) pass2_kernel(
    const float* __restrict__ inp, const float* __restrict__ od_all)
{
    __shared__ float  s_sum[CROWS * NWARP];
    __shared__ u64    s_wp[CROWS * 8];       // 7 packed weights per row (+pad)
    __shared__ float4 s_st[MAXCH * CROWS * 2];

    const int b    = blockIdx.x / CTAS_PER_B;
    const int slot = blockIdx.x % CTAS_PER_B;
    const int tid  = threadIdx.x;
    const int warp = tid >> 5, lane = tid & 31;
    const float4* ODb = reinterpret_cast<const float4*>(od_all + (size_t)(b * 2 + 1) * N * N);
    const int nch = (NCHUNKS - 1 - slot) / CTAS_PER_B + 1;

    // One-time prefetch + fused iter-0 state update; re-zero colA for replay
    for (int L = tid; L < nch * CROWS; L += TPB) {
        int i  = (slot + (L >> 3) * CTAS_PER_B) * CROWS + (L & 7);
        int gi = b * N + i;
        float4 f   = reinterpret_cast<const float4*>(inp)[gi];
        float4 csA = reinterpret_cast<float4*>(g_colA)[gi];
        reinterpret_cast<float4*>(g_colA)[gi] = make_float4(0, 0, 0, 0);
        float od1 = g_odout1[gi];
        float inv0 = 1.0f / (DELTA + f.x);
        float s60 = f.y - od1 * (f.y * inv0);
        float s61 = f.z - od1 * (f.z * inv0);
        float s62 = f.w - od1 * (f.w * inv0);
        float pop1 = f.x - od1 + csA.x;
        s_st[L * 2 + 0] = make_float4(pop1, s60, s61, s62);
        s_st[L * 2 + 1] = make_float4(csA.y, csA.z, csA.w, 0.0f);
        g_pop1[gi] = pop1;
        g_sir6[gi * 2 + 0] = make_float4(s60, s61, s62, csA.y);
        g_sir6[gi * 2 + 1] = make_float4(csA.z, csA.w, 0.0f, 0.0f);
    }
    __syncthreads();

    float4 dA[CROWS], dB[CROWS];
    {
        const float4* p = ODb + (size_t)slot * CROWS * (N / 4) + tid;
#pragma unroll
        for (int r = 0; r < CROWS; r++) dA[r] = p[r * (N / 4)];
    }

    u64 acc[2][7] = {};

    auto body = [&](float4 (&cur)[CROWS], float4 (&nxt)[CROWS], int c) {
        if (c + 1 < nch) {
            const float4* p = ODb + (size_t)(slot + (c + 1) * CTAS_PER_B) * CROWS * (N / 4) + tid;
#pragma unroll
            for (int r = 0; r < CROWS; r++) nxt[r] = p[r * (N / 4)];
        }
#pragma unroll
        for (int r = 0; r < CROWS; r++) {
            float s = (cur[r].x + cur[r].y) + (cur[r].z + cur[r].w);
#pragma unroll
            for (int o = 16; o; o >>= 1) s += __shfl_xor_sync(0xffffffffu, s, o);
            if (lane == 0) s_sum[r * NWARP + warp] = s;
        }
        __syncthreads();   // bar1

        if (warp < CROWS) {
            float s = (lane < NWARP) ? s_sum[warp * NWARP + lane] : 0.0f;
#pragma unroll
            for (int o = 8; o; o >>= 1) s += __shfl_xor_sync(0xffffffffu, s, o);
            if (lane == 0) {
                float4 a  = s_st[(c * CROWS + warp) * 2 + 0];   // pop1, s6[0..2]
                float4 bb = s_st[(c * CROWS + warp) * 2 + 1];   // s6[3..5]
                int gi = b * N + (slot + c * CTAS_PER_B) * CROWS + warp;
                float ratio = a.x / (DELTA + s);
                float sc = ratio < 1.0f ? ratio : 1.0f;
                g_odout2[gi] = sc * s;
                float inv = 1.0f / (DELTA + a.x);
                float w[7] = {sc, sc * (a.y * inv), sc * (a.z * inv), sc * (a.w * inv),
                              sc * (bb.x * inv), sc * (bb.y * inv), sc * (bb.z * inv)};
#pragma unroll
                for (int k = 0; k < 7; k++) s_wp[warp * 8 + k] = pack2(w[k], w[k]);
                s_wp[warp * 8 + 7] = 0;
            }
        }
        __syncthreads();   // bar2

#pragma unroll
        for (int r = 0; r < CROWS; r++) {
            u64 v01 = pack2(cur[r].x, cur[r].y);
            u64 v23 = pack2(cur[r].z, cur[r].w);
            const ulonglong2* wp = reinterpret_cast<const ulonglong2*>(s_wp + r * 8);
            ulonglong2 wa = wp[0], wb = wp[1], wc = wp[2], wd = wp[3];
            fma2(acc[0][0], v01, wa.x); fma2(acc[1][0], v23, wa.x);
            fma2(acc[0][1], v01, wa.y); fma2(acc[1][1], v23, wa.y);
            fma2(acc[0][2], v01, wb.x); fma2(acc[1][2], v23, wb.x);
            fma2(acc[0][3], v01, wb.y); fma2(acc[1][3], v23, wb.y);
            fma2(acc[0][4], v01, wc.x); fma2(acc[1][4], v23, wc.x);
            fma2(acc[0][5], v01, wc.y); fma2(acc[1][5], v23, wc.y);
            fma2(acc[0][6], v01, wd.x); fma2(acc[1][6], v23, wd.x);
            (void)wd.y;
        }
    };

    for (int c = 0; c < nch; c += 2) {
        body(dA, dB, c);
        if (c + 1 < nch) body(dB, dA, c + 1);
    }

#pragma unroll
    for (int h = 0; h < 2; h++) {
#pragma unroll
        for (int k = 0; k < 7; k++) {
            float lo, hi;
            unpack2(acc[h][k], lo, hi);
            atomicAdd(g_colB + ((size_t)b * N + tid * 4 + h * 2 + 0) * 8 + k, lo);
            atomicAdd(g_colB + ((size_t)b * N + tid * 4 + h * 2 + 1) * 8 + k, hi);
        }
    }
}

// ---------------------------------------------------------------------------
// Final: fuses update<6> + GEMM(12->64) + relu + concat(pop). Re-zeros colB.
// ---------------------------------------------------------------------------
__global__ void __launch_bounds__(256) final_kernel(
    const float* __restrict__ kern,
    const float* __restrict__ bias,
    float* __restrict__ out)
{
    __shared__ float s_kern[12 * 64];
    const int tid = threadIdx.x;
    for (int t = tid; t < 12 * 64; t += 256) s_kern[t] = kern[t];
    __syncthreads();

    const int rowl = tid >> 6;
    const int c    = tid & 63;
    const int gi   = blockIdx.x * 4 + rowl;

    float pop1   = g_pop1[gi];
    float odout2 = g_odout2[gi];
    float4 a   = g_sir6[gi * 2 + 0];
    float4 b4  = g_sir6[gi * 2 + 1];
    float4 cb0 = reinterpret_cast<const float4*>(g_colB)[gi * 2 + 0];
    float4 cb1 = reinterpret_cast<const float4*>(g_colB)[gi * 2 + 1];

    float dp1 = DELTA + pop1;
    float s12[12];
    s12[0] = a.x  - odout2 * dnn(a.x,  dp1);
    s12[1] = a.y  - odout2 * dnn(a.y,  dp1);
    s12[2] = a.z  - odout2 * dnn(a.z,  dp1);
    s12[3] = a.w  - odout2 * dnn(a.w,  dp1);
    s12[4] = b4.x - odout2 * dnn(b4.x, dp1);
    s12[5] = b4.y - odout2 * dnn(b4.y, dp1);
    s12[6]  = cb0.y; s12[7]  = cb0.z; s12[8]  = cb0.w;
    s12[9]  = cb1.x; s12[10] = cb1.y; s12[11] = cb1.z;

    float acc = __ldg(&bias[c]);
#pragma unroll
    for (int f = 0; f < 12; f++)
        acc = fmaf(s12[f], s_kern[f * 64 + c], acc);
    acc = fmaxf(acc, 0.0f);

    float* orow = out + (size_t)gi * 65;
    orow[1 + c] = acc;
    if (c == 0) orow[0] = pop1 - odout2 + cb0.x;

    __syncthreads();                  // all colB reads done before re-zero
    if (c < 8) g_colB[gi * 8 + c] = 0.0f;
}

// ---------------------------------------------------------------------------
extern "C" void kernel_launch(void* const* d_in, const int* in_sizes, int n_in,
                              void* d_out, int out_size) {
    const float* inp  = (const float*)d_in[0];  // input_feature (8,2048,4)
    const float* od   = (const float*)d_in[1];  // OD_all (8,2,2048,2048)
    const float* kern = (const float*)d_in[2];  // kernel (12,64)
    const float* bias = (const float*)d_in[3];  // bias (64)
    float* out = (float*)d_out;                 // (8,2048,65)

    pass1_kernel<<<GRID, TPB>>>(inp, od);
    pass2_kernel<<<GRID, TPB>>>(inp, od);
    final_kernel<<<BN / 4, 256>>>(kern, bias, out);
}